// round 11
// baseline (speedup 1.0000x reference)
#include <cuda_runtime.h>
#include <cuda_bf16.h>

// HintGenKernelBatched: masked XOR-parity gather-reduce.
//   entries:        [1000000, 5]  int32
//   padded_indices: [4096, 2048]  int32 in [0, 1e6)
//   valid_mask:     [4096, 2048]  int32 in {0, 1}
//   out:            [4096, 5]     float32 (numeric convert; values < 2^31)
//
// R10 hit ~9.8 TB/s of L2 sector traffic (the practical LTS cap) -> only
// deleting L2 bytes helps now. This round: padded 32B-aligned table
// (pre-pass, 5.3us) + R10's warp compaction + DENSE 2-lane LDG.128 gathers:
// 16 valid rows / warp instruction, exactly 1 sector + ~1 L1 wavefront per
// row, ~0.5 warp-instructions per row.
// Gather L2 bytes 201MB -> 134MB; main kernel predicted ~20.5us.

#define MAX_SUBSET 2048
#define ROW 5
#define THREADS 256
#define WARPS (THREADS / 32)
#define SLOTS_PER_WARP (MAX_SUBSET / WARPS)     // 256
#define SEG 272                                 // 256 max valid + 16 sentinels
#define MAX_ENTRIES 1000000

// Padded table: 2 int4 per row (words 0..4 + 3 zero pad). 32 MB static scratch.
__device__ __align__(32) int4 g_pad[2 * MAX_ENTRIES];

__global__ __launch_bounds__(256) void pad_entries_kernel(
    const int* __restrict__ entries, int n)
{
    const int i = blockIdx.x * blockDim.x + threadIdx.x;
    if (i < n) {
        const int* __restrict__ r = entries + (size_t)i * ROW;  // coalesced stream
        int4 a, b;
        a.x = __ldg(r + 0); a.y = __ldg(r + 1);
        a.z = __ldg(r + 2); a.w = __ldg(r + 3);
        b.x = __ldg(r + 4); b.y = 0; b.z = 0; b.w = 0;
        g_pad[2 * (size_t)i + 0] = a;           // STG.128, 32B row stride
        g_pad[2 * (size_t)i + 1] = b;
    }
}

__global__ __launch_bounds__(THREADS, 8) void hint_parity_kernel(
    const int* __restrict__ padded_indices,
    const int* __restrict__ valid_mask,
    float* __restrict__ out)
{
    __shared__ int scomp[WARPS][SEG];           // per-warp compacted indices
    __shared__ unsigned red[WARPS][ROW];

    const int h    = blockIdx.x;
    const int t    = threadIdx.x;
    const int warp = t >> 5;
    const int lane = t & 31;
    const size_t base = (size_t)h * MAX_SUBSET;

    const int4* __restrict__ idx4 =
        reinterpret_cast<const int4*>(padded_indices + base) + warp * (SLOTS_PER_WARP / 4);
    const int4* __restrict__ msk4 =
        reinterpret_cast<const int4*>(valid_mask + base) + warp * (SLOTS_PER_WARP / 4);

    // ---- Phase 1: stream + warp-local compaction (XOR order-free) ----
    unsigned cnt = 0;
    const unsigned lmask = (1u << lane) - 1u;

    #pragma unroll
    for (int i = 0; i < SLOTS_PER_WARP / (32 * 4); ++i) {   // 2 iterations
        const int4 iv = idx4[i * 32 + lane];                // LDG.128 coalesced
        const int4 mv = msk4[i * 32 + lane];

        #define COMPACT(IC, MC)                                             \
            {                                                               \
                const unsigned bal = __ballot_sync(0xffffffffu, (MC) != 0); \
                if (MC) scomp[warp][cnt + __popc(bal & lmask)] = (IC);      \
                cnt += __popc(bal);                                         \
            }
        COMPACT(iv.x, mv.x)
        COMPACT(iv.y, mv.y)
        COMPACT(iv.z, mv.z)
        COMPACT(iv.w, mv.w)
        #undef COMPACT
    }
    // sentinel pad so the dense loop rounds up to a multiple of 16 rows
    if (lane < 16) scomp[warp][cnt + lane] = -1;
    __syncwarp();

    // ---- Phase 2: dense 2-lane-group gather from the padded table ----
    // 16 groups of 2 lanes; group g takes compacted slot it*16+g; lane j
    // loads int4 j of the 32B row. One LDG.128 instruction = 16 valid rows.
    const int g = lane >> 1;
    const int j = lane & 1;

    int4 acc = make_int4(0, 0, 0, 0);           // j==1: only .x live (word4)
    const int nit = (int)((cnt + 15) >> 4);     // ~8 iterations

    #pragma unroll 4
    for (int it = 0; it < nit; ++it) {
        const int q = scomp[warp][it * 16 + g]; // LDS.32, pair-broadcast
        if (q >= 0) {
            const int4 v = __ldg(&g_pad[2 * (size_t)(unsigned)q + j]);
            acc.x ^= v.x; acc.y ^= v.y; acc.z ^= v.z; acc.w ^= v.w;
        }
    }

    // ---- Reduce the 16 groups of each warp (j parity preserved) ----
    #pragma unroll
    for (int o = 2; o <= 16; o <<= 1) {
        acc.x ^= __shfl_xor_sync(0xffffffffu, acc.x, o);
        acc.y ^= __shfl_xor_sync(0xffffffffu, acc.y, o);
        acc.z ^= __shfl_xor_sync(0xffffffffu, acc.z, o);
        acc.w ^= __shfl_xor_sync(0xffffffffu, acc.w, o);
    }

    if (lane == 0) {
        red[warp][0] = (unsigned)acc.x;
        red[warp][1] = (unsigned)acc.y;
        red[warp][2] = (unsigned)acc.z;
        red[warp][3] = (unsigned)acc.w;
    }
    if (lane == 1) {
        red[warp][4] = (unsigned)acc.x;
    }
    __syncthreads();

    // ---- Fold 8 warps, store float32 ----
    if (t < ROW) {
        unsigned v = red[0][t];
        #pragma unroll
        for (int w = 1; w < WARPS; ++w) v ^= red[w][t];
        out[(size_t)h * ROW + t] = (float)v;    // numeric convert, values < 2^31
    }
}

extern "C" void kernel_launch(void* const* d_in, const int* in_sizes, int n_in,
                              void* d_out, int out_size)
{
    const int* entries        = (const int*)d_in[0];
    const int* padded_indices = (const int*)d_in[1];
    const int* valid_mask     = (const int*)d_in[2];
    float* out = (float*)d_out;

    int n_entries = in_sizes[0] / ROW;          // 1,000,000
    if (n_entries > MAX_ENTRIES) n_entries = MAX_ENTRIES;
    const int num_hints = out_size / ROW;       // 4096

    pad_entries_kernel<<<(n_entries + 255) / 256, 256>>>(entries, n_entries);
    hint_parity_kernel<<<num_hints, THREADS>>>(padded_indices, valid_mask, out);
}

// round 12
// speedup vs baseline: 1.3088x; 1.3088x over previous
#include <cuda_runtime.h>
#include <cuda_bf16.h>

// HintGenKernelBatched: masked XOR-parity gather-reduce.
//   entries:        [1000000, 5]  int32
//   padded_indices: [4096, 2048]  int32 in [0, 1e6)
//   valid_mask:     [4096, 2048]  int32 in {0, 1}
//   out:            [4096, 5]     float32 (numeric convert; values < 2^31)
//
// R11 post-mortem: padded-table relayout RETIRED (L2 capacity thrash: scratch
// pushed resident set past L2, DRAM refills returned). Steady state works
// because all inputs (84MB) fit in L2; never enlarge the resident set.
// R10 sits at ~265MB LTS traffic / 27us ~ near the LTS roof; bytes are
// irreducible, so this round attacks latency efficiency: phase-1 compaction
// ballots are now ISSUED INDEPENDENTLY (8 parallel ballots + scalar popc
// prefix) instead of a 16-step serial cnt chain (~300+ cyc/warp saved on the
// critical path before the first gather can issue).

#define MAX_SUBSET 2048
#define ROW 5
#define THREADS 256
#define WARPS (THREADS / 32)
#define SLOTS_PER_WARP (MAX_SUBSET / WARPS)     // 256
#define SEG 264                                 // 256 max valid + sentinels

__global__ __launch_bounds__(THREADS, 8) void hint_parity_kernel(
    const int* __restrict__ entries,
    const int* __restrict__ padded_indices,
    const int* __restrict__ valid_mask,
    float* __restrict__ out)
{
    __shared__ int scomp[WARPS][SEG];           // per-warp compacted indices
    __shared__ unsigned red[WARPS][ROW];

    const int h    = blockIdx.x;
    const int t    = threadIdx.x;
    const int warp = t >> 5;
    const int lane = t & 31;
    const size_t base = (size_t)h * MAX_SUBSET;

    const int4* __restrict__ idx4 =
        reinterpret_cast<const int4*>(padded_indices + base) + warp * (SLOTS_PER_WARP / 4);
    const int4* __restrict__ msk4 =
        reinterpret_cast<const int4*>(valid_mask + base) + warp * (SLOTS_PER_WARP / 4);

    // ---- Phase 1: stream + warp compaction, ballots issued in parallel ----
    const unsigned lmask = (1u << lane) - 1u;

    // All streamed loads up front (4x LDG.128 per lane, full MLP)
    const int4 iv0 = idx4[lane];
    const int4 iv1 = idx4[32 + lane];
    const int4 mv0 = msk4[lane];
    const int4 mv1 = msk4[32 + lane];

    // 8 independent ballots (no serial dependence between them)
    unsigned b0 = __ballot_sync(0xffffffffu, mv0.x != 0);
    unsigned b1 = __ballot_sync(0xffffffffu, mv0.y != 0);
    unsigned b2 = __ballot_sync(0xffffffffu, mv0.z != 0);
    unsigned b3 = __ballot_sync(0xffffffffu, mv0.w != 0);
    unsigned b4 = __ballot_sync(0xffffffffu, mv1.x != 0);
    unsigned b5 = __ballot_sync(0xffffffffu, mv1.y != 0);
    unsigned b6 = __ballot_sync(0xffffffffu, mv1.z != 0);
    unsigned b7 = __ballot_sync(0xffffffffu, mv1.w != 0);

    // Scalar popc prefix (cheap IADD chain)
    const unsigned o0 = 0;
    const unsigned o1 = o0 + __popc(b0);
    const unsigned o2 = o1 + __popc(b1);
    const unsigned o3 = o2 + __popc(b2);
    const unsigned o4 = o3 + __popc(b3);
    const unsigned o5 = o4 + __popc(b4);
    const unsigned o6 = o5 + __popc(b5);
    const unsigned o7 = o6 + __popc(b6);
    const unsigned cnt = o7 + __popc(b7);

    // 8 independent compacted stores
    if (mv0.x) scomp[warp][o0 + __popc(b0 & lmask)] = iv0.x;
    if (mv0.y) scomp[warp][o1 + __popc(b1 & lmask)] = iv0.y;
    if (mv0.z) scomp[warp][o2 + __popc(b2 & lmask)] = iv0.z;
    if (mv0.w) scomp[warp][o3 + __popc(b3 & lmask)] = iv0.w;
    if (mv1.x) scomp[warp][o4 + __popc(b4 & lmask)] = iv1.x;
    if (mv1.y) scomp[warp][o5 + __popc(b5 & lmask)] = iv1.y;
    if (mv1.z) scomp[warp][o6 + __popc(b6 & lmask)] = iv1.z;
    if (mv1.w) scomp[warp][o7 + __popc(b7 & lmask)] = iv1.w;

    // sentinel pad so the dense loop rounds up to a multiple of 4
    if (lane < 4) scomp[warp][cnt + lane] = -1;
    __syncwarp();

    // ---- Phase 2: dense cooperative gather (R10 geometry, proven) ----
    // 4 groups of 8 lanes; group g takes compacted slot it*4+g; lane j<5
    // loads word j of that row. Every LDG covers 4 valid rows.
    const int j  = lane & 7;
    const int g  = lane >> 3;
    const bool wl = (j < ROW);

    unsigned acc = 0;
    const int nit = (int)((cnt + 3) >> 2);

    #pragma unroll 4
    for (int it = 0; it < nit; ++it) {
        const int q = scomp[warp][it * 4 + g];  // LDS.32, group-broadcast
        if (wl && q >= 0) {
            acc ^= (unsigned)__ldg(entries + (size_t)(unsigned)q * ROW + j);
        }
    }

    // ---- Reduce the 4 groups of each warp ----
    acc ^= __shfl_xor_sync(0xffffffffu, acc, 8);
    acc ^= __shfl_xor_sync(0xffffffffu, acc, 16);

    // lanes 0..4 hold the warp's parity for words 0..4
    if (lane < ROW) red[warp][lane] = acc;
    __syncthreads();

    // ---- Fold 8 warps, store float32 ----
    if (t < ROW) {
        unsigned v = red[0][t];
        #pragma unroll
        for (int w = 1; w < WARPS; ++w) v ^= red[w][t];
        out[(size_t)h * ROW + t] = (float)v;    // numeric convert, values < 2^31
    }
}

extern "C" void kernel_launch(void* const* d_in, const int* in_sizes, int n_in,
                              void* d_out, int out_size)
{
    const int* entries        = (const int*)d_in[0];
    const int* padded_indices = (const int*)d_in[1];
    const int* valid_mask     = (const int*)d_in[2];
    float* out = (float*)d_out;

    const int num_hints = out_size / ROW;  // 4096
    hint_parity_kernel<<<num_hints, THREADS>>>(entries, padded_indices, valid_mask, out);
}